// round 3
// baseline (speedup 1.0000x reference)
#include <cuda_runtime.h>

#define NN 100000
#define EE 1600000
#define TOT (EE + NN)
#define FIN 50
#define HIDW 40
#define CDIM 121

// ---------------- scratch (device globals; no runtime allocation) ----------
__device__ int   g_cnt[NN];
__device__ int   g_rowptr[NN + 1];
__device__ int   g_colsrc[TOT];
__device__ float g_xw[NN * 726];      // largest per-layer xw (layer3: H*D = 726)
__device__ float g_asrc[NN * 6];
__device__ float g_adst[NN * 6];
__device__ float g_skip[NN * CDIM];   // skip-linear output (max 121 cols)
__device__ float g_hA[NN * HIDW];
__device__ float g_hB[NN * HIDW];

// ---------------- CSR construction ----------------------------------------
__global__ void k_init_counts(int n) {
    int i = blockIdx.x * blockDim.x + threadIdx.x;
    if (i < n) g_cnt[i] = 1;   // self-loop
}

__global__ void k_hist(const int* __restrict__ dst, int e) {
    int i = blockIdx.x * blockDim.x + threadIdx.x;
    if (i < e) atomicAdd(&g_cnt[dst[i]], 1);
}

__global__ void k_scan(int n) {
    __shared__ int s_warp[32];
    __shared__ int s_carry;
    int tid = threadIdx.x, lane = tid & 31, w = tid >> 5;
    if (tid == 0) { s_carry = 0; g_rowptr[0] = 0; }
    __syncthreads();
    for (int base = 0; base < n; base += 1024) {
        int i = base + tid;
        int v = (i < n) ? g_cnt[i] : 0;
        int x = v;
        #pragma unroll
        for (int o = 1; o < 32; o <<= 1) {
            int y = __shfl_up_sync(0xffffffffu, x, o);
            if (lane >= o) x += y;
        }
        if (lane == 31) s_warp[w] = x;
        __syncthreads();
        if (w == 0) {
            int y = s_warp[lane];
            #pragma unroll
            for (int o = 1; o < 32; o <<= 1) {
                int z = __shfl_up_sync(0xffffffffu, y, o);
                if (lane >= o) y += z;
            }
            s_warp[lane] = y;
        }
        __syncthreads();
        int incl = x + (w > 0 ? s_warp[w - 1] : 0) + s_carry;
        if (i < n) g_rowptr[i + 1] = incl;
        __syncthreads();
        if (tid == 1023) s_carry = incl;
        __syncthreads();
    }
}

__global__ void k_zero_counts(int n) {
    int i = blockIdx.x * blockDim.x + threadIdx.x;
    if (i < n) g_cnt[i] = 0;
}

__global__ void k_scatter_self(int n) {
    int i = blockIdx.x * blockDim.x + threadIdx.x;
    if (i < n) {
        int pos = g_rowptr[i] + atomicAdd(&g_cnt[i], 1);
        g_colsrc[pos] = i;
    }
}

__global__ void k_scatter_edge(const int* __restrict__ src, const int* __restrict__ dst, int e) {
    int i = blockIdx.x * blockDim.x + threadIdx.x;
    if (i < e) {
        int d = dst[i];
        int pos = g_rowptr[d] + atomicAdd(&g_cnt[d], 1);
        g_colsrc[pos] = src[i];
    }
}

// ---------------- dense GEMM: out[n,C] = A[n,K] @ B[K,C] (+bias) ----------
template <int K>
__launch_bounds__(256)
__global__ void gemm_kernel(const float* __restrict__ A, const float* __restrict__ B,
                            const float* __restrict__ bias, float* __restrict__ out,
                            int n, int C) {
    __shared__ float sAT[K][68];   // [k][node]
    __shared__ float sB[K][68];    // [k][col]
    int n0 = blockIdx.x * 64, c0 = blockIdx.y * 64;
    for (int idx = threadIdx.x; idx < 64 * K; idx += 256) {
        int i = idx / K, k = idx - i * K;
        int node = n0 + i;
        sAT[k][i] = (node < n) ? A[(size_t)node * K + k] : 0.f;
    }
    for (int idx = threadIdx.x; idx < 64 * K; idx += 256) {
        int k = idx >> 6, j = idx & 63;
        int c = c0 + j;
        sB[k][j] = (c < C) ? B[k * C + c] : 0.f;
    }
    __syncthreads();
    int tx = threadIdx.x & 15, ty = threadIdx.x >> 4;
    float acc[4][4];
    #pragma unroll
    for (int i = 0; i < 4; i++)
        #pragma unroll
        for (int j = 0; j < 4; j++) acc[i][j] = 0.f;
    #pragma unroll 10
    for (int k = 0; k < K; k++) {
        float a[4], b[4];
        #pragma unroll
        for (int i = 0; i < 4; i++) a[i] = sAT[k][ty * 4 + i];
        #pragma unroll
        for (int j = 0; j < 4; j++) b[j] = sB[k][tx * 4 + j];
        #pragma unroll
        for (int i = 0; i < 4; i++)
            #pragma unroll
            for (int j = 0; j < 4; j++) acc[i][j] = fmaf(a[i], b[j], acc[i][j]);
    }
    #pragma unroll
    for (int i = 0; i < 4; i++) {
        int node = n0 + ty * 4 + i;
        if (node >= n) continue;
        #pragma unroll
        for (int j = 0; j < 4; j++) {
            int c = c0 + tx * 4 + j;
            if (c < C) out[(size_t)node * C + c] = acc[i][j] + (bias ? bias[c] : 0.f);
        }
    }
}

// ---------------- attention coefficients -----------------------------------
template <int H, int D>
__global__ void attn_kernel(const float* __restrict__ xw, const float* __restrict__ av,
                            const float* __restrict__ adv, float* __restrict__ asrc,
                            float* __restrict__ adst, int n) {
    int idx = blockIdx.x * blockDim.x + threadIdx.x;
    if (idx >= n * H) return;
    int node = idx / H, h = idx - node * H;
    const float* row = xw + (size_t)node * (H * D) + h * D;
    float s1 = 0.f, s2 = 0.f;
    #pragma unroll 8
    for (int d = 0; d < D; d++) {
        float v = row[d];
        s1 = fmaf(v, av[h * D + d], s1);
        s2 = fmaf(v, adv[h * D + d], s2);
    }
    asrc[idx] = s1;
    adst[idx] = s2;
}

// ---------------- GAT aggregation: warp per destination node ---------------
// concat version (layers 1,2): out = elu(agg + bias + skip)
template <int H, int D, int CPL>
__launch_bounds__(128)
__global__ void agg_concat_kernel(const float* __restrict__ xw,
                                  const float* __restrict__ asrc,
                                  const float* __restrict__ adst,
                                  const float* __restrict__ bias,
                                  const float* __restrict__ skip,
                                  float* __restrict__ out, int n) {
    constexpr int C = H * D;
    int node = (blockIdx.x * blockDim.x + threadIdx.x) >> 5;
    int lane = threadIdx.x & 31;
    if (node >= n) return;
    int beg = g_rowptr[node], end = g_rowptr[node + 1];
    float adn[H], mx[H], sm[H];
    #pragma unroll
    for (int h = 0; h < H; h++) { adn[h] = adst[node * H + h]; mx[h] = -1e30f; sm[h] = 0.f; }
    // pass 1: segment max
    for (int i = beg + lane; i < end; i += 32) {
        int s = g_colsrc[i];
        #pragma unroll
        for (int h = 0; h < H; h++) {
            float ev = asrc[s * H + h] + adn[h];
            ev = ev > 0.f ? ev : 0.2f * ev;
            mx[h] = fmaxf(mx[h], ev);
        }
    }
    #pragma unroll
    for (int h = 0; h < H; h++)
        for (int o = 16; o > 0; o >>= 1)
            mx[h] = fmaxf(mx[h], __shfl_xor_sync(0xffffffffu, mx[h], o));
    // pass 2: segment sum of exp
    for (int i = beg + lane; i < end; i += 32) {
        int s = g_colsrc[i];
        #pragma unroll
        for (int h = 0; h < H; h++) {
            float ev = asrc[s * H + h] + adn[h];
            ev = ev > 0.f ? ev : 0.2f * ev;
            sm[h] += __expf(ev - mx[h]);
        }
    }
    #pragma unroll
    for (int h = 0; h < H; h++) {
        for (int o = 16; o > 0; o >>= 1)
            sm[h] += __shfl_xor_sync(0xffffffffu, sm[h], o);
        sm[h] = 1.f / sm[h];
    }
    // pass 3: weighted gather-accumulate (whole warp per edge)
    float acc[CPL];
    int hed[CPL];
    #pragma unroll
    for (int j = 0; j < CPL; j++) {
        acc[j] = 0.f;
        int c = lane + 32 * j;
        hed[j] = (c < C) ? c / D : 0;
    }
    float adl = (lane < H) ? adn[lane] : 0.f;
    float mxl = (lane < H) ? mx[lane] : 0.f;
    float sml = (lane < H) ? sm[lane] : 0.f;
    for (int i = beg; i < end; i++) {
        int s = g_colsrc[i];
        float wt = 0.f;
        if (lane < H) {
            float ev = asrc[s * H + lane] + adl;
            ev = ev > 0.f ? ev : 0.2f * ev;
            wt = __expf(ev - mxl) * sml;
        }
        #pragma unroll
        for (int j = 0; j < CPL; j++) {
            float w = __shfl_sync(0xffffffffu, wt, hed[j]);
            int c = lane + 32 * j;
            if (c < C) acc[j] = fmaf(xw[s * C + c], w, acc[j]);
        }
    }
    #pragma unroll
    for (int j = 0; j < CPL; j++) {
        int c = lane + 32 * j;
        if (c < C) {
            float v = acc[j] + bias[c] + skip[node * C + c];
            out[node * C + c] = v > 0.f ? v : (__expf(v) - 1.f);
        }
    }
}

// mean version (layer 3, heads=6, D=121): out = mean_h(agg) + bias + skip (no elu)
__launch_bounds__(128)
__global__ void agg_mean_kernel(const float* __restrict__ xw,
                                const float* __restrict__ asrc,
                                const float* __restrict__ adst,
                                const float* __restrict__ bias,
                                const float* __restrict__ skip,
                                float* __restrict__ out, int n) {
    constexpr int H = 6, D = 121, C = 726, CPL = 23;
    __shared__ float s_agg[4][C];
    int node = (blockIdx.x * blockDim.x + threadIdx.x) >> 5;
    int lane = threadIdx.x & 31;
    int wl = threadIdx.x >> 5;
    if (node >= n) return;
    int beg = g_rowptr[node], end = g_rowptr[node + 1];
    float adn[H], mx[H], sm[H];
    #pragma unroll
    for (int h = 0; h < H; h++) { adn[h] = adst[node * H + h]; mx[h] = -1e30f; sm[h] = 0.f; }
    for (int i = beg + lane; i < end; i += 32) {
        int s = g_colsrc[i];
        #pragma unroll
        for (int h = 0; h < H; h++) {
            float ev = asrc[s * H + h] + adn[h];
            ev = ev > 0.f ? ev : 0.2f * ev;
            mx[h] = fmaxf(mx[h], ev);
        }
    }
    #pragma unroll
    for (int h = 0; h < H; h++)
        for (int o = 16; o > 0; o >>= 1)
            mx[h] = fmaxf(mx[h], __shfl_xor_sync(0xffffffffu, mx[h], o));
    for (int i = beg + lane; i < end; i += 32) {
        int s = g_colsrc[i];
        #pragma unroll
        for (int h = 0; h < H; h++) {
            float ev = asrc[s * H + h] + adn[h];
            ev = ev > 0.f ? ev : 0.2f * ev;
            sm[h] += __expf(ev - mx[h]);
        }
    }
    #pragma unroll
    for (int h = 0; h < H; h++) {
        for (int o = 16; o > 0; o >>= 1)
            sm[h] += __shfl_xor_sync(0xffffffffu, sm[h], o);
        sm[h] = 1.f / sm[h];
    }
    float acc[CPL];
    int hed[CPL];
    #pragma unroll
    for (int j = 0; j < CPL; j++) {
        acc[j] = 0.f;
        int c = lane + 32 * j;
        hed[j] = (c < C) ? c / D : 0;
    }
    float adl = (lane < H) ? adn[lane] : 0.f;
    float mxl = (lane < H) ? mx[lane] : 0.f;
    float sml = (lane < H) ? sm[lane] : 0.f;
    for (int i = beg; i < end; i++) {
        int s = g_colsrc[i];
        float wt = 0.f;
        if (lane < H) {
            float ev = asrc[s * H + lane] + adl;
            ev = ev > 0.f ? ev : 0.2f * ev;
            wt = __expf(ev - mxl) * sml;
        }
        #pragma unroll
        for (int j = 0; j < CPL; j++) {
            float w = __shfl_sync(0xffffffffu, wt, hed[j]);
            int c = lane + 32 * j;
            if (c < C) acc[j] = fmaf(xw[s * C + c], w, acc[j]);
        }
    }
    #pragma unroll
    for (int j = 0; j < CPL; j++) {
        int c = lane + 32 * j;
        if (c < C) s_agg[wl][c] = acc[j];
    }
    __syncwarp();
    for (int jc = lane; jc < D; jc += 32) {
        float v = 0.f;
        #pragma unroll
        for (int h = 0; h < H; h++) v += s_agg[wl][h * D + jc];
        out[node * D + jc] = v * (1.f / 6.f) + bias[jc] + skip[node * D + jc];
    }
}

// ---------------- launcher --------------------------------------------------
extern "C" void kernel_launch(void* const* d_in, const int* in_sizes, int n_in,
                              void* d_out, int out_size) {
    const float* x   = (const float*)d_in[0];
    const int*   ei  = (const int*)d_in[1];
    const float* W1  = (const float*)d_in[2];
    const float* as1 = (const float*)d_in[3];
    const float* ad1 = (const float*)d_in[4];
    const float* b1  = (const float*)d_in[5];
    const float* lw1 = (const float*)d_in[6];
    const float* lb1 = (const float*)d_in[7];
    const float* W2  = (const float*)d_in[8];
    const float* as2 = (const float*)d_in[9];
    const float* ad2 = (const float*)d_in[10];
    const float* b2  = (const float*)d_in[11];
    const float* lw2 = (const float*)d_in[12];
    const float* lb2 = (const float*)d_in[13];
    const float* W3  = (const float*)d_in[14];
    const float* as3 = (const float*)d_in[15];
    const float* ad3 = (const float*)d_in[16];
    const float* b3  = (const float*)d_in[17];
    const float* lw3 = (const float*)d_in[18];
    const float* lb3 = (const float*)d_in[19];
    float* out = (float*)d_out;

    int n = in_sizes[0] / FIN;
    int e = in_sizes[1] / 2;
    const int* srcp = ei;
    const int* dstp = ei + e;

    float *xw, *asrc, *adst, *skip, *hA, *hB;
    cudaGetSymbolAddress((void**)&xw, g_xw);
    cudaGetSymbolAddress((void**)&asrc, g_asrc);
    cudaGetSymbolAddress((void**)&adst, g_adst);
    cudaGetSymbolAddress((void**)&skip, g_skip);
    cudaGetSymbolAddress((void**)&hA, g_hA);
    cudaGetSymbolAddress((void**)&hB, g_hB);

    // ---- CSR build (dst-sorted adjacency incl. self-loops) ----
    k_init_counts<<<(n + 255) / 256, 256>>>(n);
    k_hist<<<(e + 255) / 256, 256>>>(dstp, e);
    k_scan<<<1, 1024>>>(n);
    k_zero_counts<<<(n + 255) / 256, 256>>>(n);
    k_scatter_self<<<(n + 255) / 256, 256>>>(n);
    k_scatter_edge<<<(e + 255) / 256, 256>>>(srcp, dstp, e);

    int nb64 = (n + 63) / 64;

    // ---- layer 1: GAT(50 -> 4x10, concat) + x@lw1 + lb1, elu ----
    gemm_kernel<FIN><<<dim3(nb64, 1), 256>>>(x, W1, nullptr, xw, n, 40);
    attn_kernel<4, 10><<<(n * 4 + 255) / 256, 256>>>(xw, as1, ad1, asrc, adst, n);
    gemm_kernel<FIN><<<dim3(nb64, 1), 256>>>(x, lw1, lb1, skip, n, 40);
    agg_concat_kernel<4, 10, 2><<<(n + 3) / 4, 128>>>(xw, asrc, adst, b1, skip, hA, n);

    // ---- layer 2: GAT(40 -> 4x10, concat) + hA@lw2 + lb2, elu ----
    gemm_kernel<HIDW><<<dim3(nb64, 1), 256>>>(hA, W2, nullptr, xw, n, 40);
    attn_kernel<4, 10><<<(n * 4 + 255) / 256, 256>>>(xw, as2, ad2, asrc, adst, n);
    gemm_kernel<HIDW><<<dim3(nb64, 1), 256>>>(hA, lw2, lb2, skip, n, 40);
    agg_concat_kernel<4, 10, 2><<<(n + 3) / 4, 128>>>(xw, asrc, adst, b2, skip, hB, n);

    // ---- layer 3: GAT(40 -> 6x121, mean) + hB@lw3 + lb3 ----
    gemm_kernel<HIDW><<<dim3(nb64, (726 + 63) / 64), 256>>>(hB, W3, nullptr, xw, n, 726);
    attn_kernel<6, 121><<<(n * 6 + 255) / 256, 256>>>(xw, as3, ad3, asrc, adst, n);
    gemm_kernel<HIDW><<<dim3(nb64, (121 + 63) / 64), 256>>>(hB, lw3, lb3, skip, n, 121);
    agg_mean_kernel<<<(n + 3) / 4, 128>>>(xw, asrc, adst, b3, skip, out, n);
}

// round 11
// speedup vs baseline: 1.1335x; 1.1335x over previous
#include <cuda_runtime.h>
#include <cuda_fp16.h>

#define NN 100000
#define EE 1600000
#define TOT (EE + NN)
#define FIN 50
#define HIDW 40
#define CDIM 121

// ---------------- scratch (device globals; no runtime allocation) ----------
__device__ int    g_cnt[NN];
__device__ int    g_rowptr[NN + 1];
__device__ int    g_colsrc[TOT];
__device__ float  g_xw[NN * HIDW];    // fp32 xw for layers 1,2 (40 cols)
__device__ __half g_xwh[NN * 726];    // fp16 xw for layer 3 (726 cols)
__device__ float  g_asrc[NN * 6];
__device__ float  g_adst[NN * 6];
__device__ float  g_skip[NN * CDIM];
__device__ float  g_hA[NN * HIDW];
__device__ float  g_hB[NN * HIDW];

// ---------------- CSR construction ----------------------------------------
__global__ void k_init_counts(int n) {
    int i = blockIdx.x * blockDim.x + threadIdx.x;
    if (i < n) g_cnt[i] = 1;   // self-loop
}

__global__ void k_hist(const int* __restrict__ dst, int e) {
    int i = blockIdx.x * blockDim.x + threadIdx.x;
    if (i < e) atomicAdd(&g_cnt[dst[i]], 1);
}

__global__ void k_scan(int n) {
    __shared__ int s_warp[32];
    __shared__ int s_carry;
    int tid = threadIdx.x, lane = tid & 31, w = tid >> 5;
    if (tid == 0) { s_carry = 0; g_rowptr[0] = 0; }
    __syncthreads();
    for (int base = 0; base < n; base += 1024) {
        int i = base + tid;
        int v = (i < n) ? g_cnt[i] : 0;
        int x = v;
        #pragma unroll
        for (int o = 1; o < 32; o <<= 1) {
            int y = __shfl_up_sync(0xffffffffu, x, o);
            if (lane >= o) x += y;
        }
        if (lane == 31) s_warp[w] = x;
        __syncthreads();
        if (w == 0) {
            int y = s_warp[lane];
            #pragma unroll
            for (int o = 1; o < 32; o <<= 1) {
                int z = __shfl_up_sync(0xffffffffu, y, o);
                if (lane >= o) y += z;
            }
            s_warp[lane] = y;
        }
        __syncthreads();
        int incl = x + (w > 0 ? s_warp[w - 1] : 0) + s_carry;
        if (i < n) g_rowptr[i + 1] = incl;
        __syncthreads();
        if (tid == 1023) s_carry = incl;
        __syncthreads();
    }
}

__global__ void k_zero_counts(int n) {
    int i = blockIdx.x * blockDim.x + threadIdx.x;
    if (i < n) g_cnt[i] = 0;
}

__global__ void k_scatter_self(int n) {
    int i = blockIdx.x * blockDim.x + threadIdx.x;
    if (i < n) {
        int pos = g_rowptr[i] + atomicAdd(&g_cnt[i], 1);
        g_colsrc[pos] = i;
    }
}

__global__ void k_scatter_edge(const int* __restrict__ src, const int* __restrict__ dst, int e) {
    int i = blockIdx.x * blockDim.x + threadIdx.x;
    if (i < e) {
        int d = dst[i];
        int pos = g_rowptr[d] + atomicAdd(&g_cnt[d], 1);
        g_colsrc[pos] = src[i];
    }
}

// ---------------- dense GEMM: out[n,C] = A[n,K] @ B[K,C] (+bias) ----------
template <int K, typename OUT_T>
__launch_bounds__(256)
__global__ void gemm_kernel(const float* __restrict__ A, const float* __restrict__ B,
                            const float* __restrict__ bias, OUT_T* __restrict__ out,
                            int n, int C) {
    __shared__ float sAT[K][68];   // [k][node]
    __shared__ float sB[K][68];    // [k][col]
    int n0 = blockIdx.x * 64, c0 = blockIdx.y * 64;
    for (int idx = threadIdx.x; idx < 64 * K; idx += 256) {
        int i = idx / K, k = idx - i * K;
        int node = n0 + i;
        sAT[k][i] = (node < n) ? A[(size_t)node * K + k] : 0.f;
    }
    for (int idx = threadIdx.x; idx < 64 * K; idx += 256) {
        int k = idx >> 6, j = idx & 63;
        int c = c0 + j;
        sB[k][j] = (c < C) ? B[k * C + c] : 0.f;
    }
    __syncthreads();
    int tx = threadIdx.x & 15, ty = threadIdx.x >> 4;
    float acc[4][4];
    #pragma unroll
    for (int i = 0; i < 4; i++)
        #pragma unroll
        for (int j = 0; j < 4; j++) acc[i][j] = 0.f;
    #pragma unroll 10
    for (int k = 0; k < K; k++) {
        float a[4], b[4];
        #pragma unroll
        for (int i = 0; i < 4; i++) a[i] = sAT[k][ty * 4 + i];
        #pragma unroll
        for (int j = 0; j < 4; j++) b[j] = sB[k][tx * 4 + j];
        #pragma unroll
        for (int i = 0; i < 4; i++)
            #pragma unroll
            for (int j = 0; j < 4; j++) acc[i][j] = fmaf(a[i], b[j], acc[i][j]);
    }
    #pragma unroll
    for (int i = 0; i < 4; i++) {
        int node = n0 + ty * 4 + i;
        if (node >= n) continue;
        #pragma unroll
        for (int j = 0; j < 4; j++) {
            int c = c0 + tx * 4 + j;
            if (c < C) {
                float v = acc[i][j] + (bias ? bias[c] : 0.f);
                out[(size_t)node * C + c] = (OUT_T)v;
            }
        }
    }
}

// ---------------- attention coefficients (fp32 xw) -------------------------
template <int H, int D>
__global__ void attn_kernel(const float* __restrict__ xw, const float* __restrict__ av,
                            const float* __restrict__ adv, float* __restrict__ asrc,
                            float* __restrict__ adst, int n) {
    int idx = blockIdx.x * blockDim.x + threadIdx.x;
    if (idx >= n * H) return;
    int node = idx / H, h = idx - node * H;
    const float* row = xw + (size_t)node * (H * D) + h * D;
    float s1 = 0.f, s2 = 0.f;
    #pragma unroll 8
    for (int d = 0; d < D; d++) {
        float v = row[d];
        s1 = fmaf(v, av[h * D + d], s1);
        s2 = fmaf(v, adv[h * D + d], s2);
    }
    asrc[idx] = s1;
    adst[idx] = s2;
}

// attention coefficients reading fp16 xw (layer 3)
template <int H, int D>
__global__ void attn_kernel_h(const __half* __restrict__ xw, const float* __restrict__ av,
                              const float* __restrict__ adv, float* __restrict__ asrc,
                              float* __restrict__ adst, int n) {
    int idx = blockIdx.x * blockDim.x + threadIdx.x;
    if (idx >= n * H) return;
    int node = idx / H, h = idx - node * H;
    const __half* row = xw + (size_t)node * (H * D) + h * D;
    float s1 = 0.f, s2 = 0.f;
    #pragma unroll 11
    for (int d = 0; d < D; d++) {
        float v = __half2float(row[d]);
        s1 = fmaf(v, av[h * D + d], s1);
        s2 = fmaf(v, adv[h * D + d], s2);
    }
    asrc[idx] = s1;
    adst[idx] = s2;
}

// ---------------- GAT aggregation: warp per destination node ---------------
// concat version (layers 1,2): out = elu(agg + bias + skip)
template <int H, int D, int CPL>
__launch_bounds__(128)
__global__ void agg_concat_kernel(const float* __restrict__ xw,
                                  const float* __restrict__ asrc,
                                  const float* __restrict__ adst,
                                  const float* __restrict__ bias,
                                  const float* __restrict__ skip,
                                  float* __restrict__ out, int n) {
    constexpr int C = H * D;
    int node = (blockIdx.x * blockDim.x + threadIdx.x) >> 5;
    int lane = threadIdx.x & 31;
    if (node >= n) return;
    int beg = g_rowptr[node], end = g_rowptr[node + 1];
    float adn[H], mx[H], sm[H];
    #pragma unroll
    for (int h = 0; h < H; h++) { adn[h] = adst[node * H + h]; mx[h] = -1e30f; sm[h] = 0.f; }
    // pass 1: segment max
    for (int i = beg + lane; i < end; i += 32) {
        int s = g_colsrc[i];
        #pragma unroll
        for (int h = 0; h < H; h++) {
            float ev = asrc[s * H + h] + adn[h];
            ev = ev > 0.f ? ev : 0.2f * ev;
            mx[h] = fmaxf(mx[h], ev);
        }
    }
    #pragma unroll
    for (int h = 0; h < H; h++)
        for (int o = 16; o > 0; o >>= 1)
            mx[h] = fmaxf(mx[h], __shfl_xor_sync(0xffffffffu, mx[h], o));
    // pass 2: segment sum of exp
    for (int i = beg + lane; i < end; i += 32) {
        int s = g_colsrc[i];
        #pragma unroll
        for (int h = 0; h < H; h++) {
            float ev = asrc[s * H + h] + adn[h];
            ev = ev > 0.f ? ev : 0.2f * ev;
            sm[h] += __expf(ev - mx[h]);
        }
    }
    #pragma unroll
    for (int h = 0; h < H; h++) {
        for (int o = 16; o > 0; o >>= 1)
            sm[h] += __shfl_xor_sync(0xffffffffu, sm[h], o);
        sm[h] = 1.f / sm[h];
    }
    // pass 3: weighted gather-accumulate (whole warp per edge)
    float acc[CPL];
    int hed[CPL];
    #pragma unroll
    for (int j = 0; j < CPL; j++) {
        acc[j] = 0.f;
        int c = lane + 32 * j;
        hed[j] = (c < C) ? c / D : 0;
    }
    float adl = (lane < H) ? adn[lane] : 0.f;
    float mxl = (lane < H) ? mx[lane] : 0.f;
    float sml = (lane < H) ? sm[lane] : 0.f;
    for (int i = beg; i < end; i++) {
        int s = g_colsrc[i];
        float wt = 0.f;
        if (lane < H) {
            float ev = asrc[s * H + lane] + adl;
            ev = ev > 0.f ? ev : 0.2f * ev;
            wt = __expf(ev - mxl) * sml;
        }
        #pragma unroll
        for (int j = 0; j < CPL; j++) {
            float w = __shfl_sync(0xffffffffu, wt, hed[j]);
            int c = lane + 32 * j;
            if (c < C) acc[j] = fmaf(xw[s * C + c], w, acc[j]);
        }
    }
    #pragma unroll
    for (int j = 0; j < CPL; j++) {
        int c = lane + 32 * j;
        if (c < C) {
            float v = acc[j] + bias[c] + skip[node * C + c];
            out[node * C + c] = v > 0.f ? v : (__expf(v) - 1.f);
        }
    }
}

// mean version (layer 3, heads=6, D=121, fp16 values): out = mean_h(agg) + bias + skip
__launch_bounds__(128)
__global__ void agg_mean_kernel(const __half* __restrict__ xw,
                                const float* __restrict__ asrc,
                                const float* __restrict__ adst,
                                const float* __restrict__ bias,
                                const float* __restrict__ skip,
                                float* __restrict__ out, int n) {
    constexpr int H = 6, D = 121, C = 726, CPL = 23;
    __shared__ float s_agg[4][C];
    int node = (blockIdx.x * blockDim.x + threadIdx.x) >> 5;
    int lane = threadIdx.x & 31;
    int wl = threadIdx.x >> 5;
    if (node >= n) return;
    int beg = g_rowptr[node], end = g_rowptr[node + 1];
    float adn[H], mx[H], sm[H];
    #pragma unroll
    for (int h = 0; h < H; h++) { adn[h] = adst[node * H + h]; mx[h] = -1e30f; sm[h] = 0.f; }
    for (int i = beg + lane; i < end; i += 32) {
        int s = g_colsrc[i];
        #pragma unroll
        for (int h = 0; h < H; h++) {
            float ev = asrc[s * H + h] + adn[h];
            ev = ev > 0.f ? ev : 0.2f * ev;
            mx[h] = fmaxf(mx[h], ev);
        }
    }
    #pragma unroll
    for (int h = 0; h < H; h++)
        for (int o = 16; o > 0; o >>= 1)
            mx[h] = fmaxf(mx[h], __shfl_xor_sync(0xffffffffu, mx[h], o));
    for (int i = beg + lane; i < end; i += 32) {
        int s = g_colsrc[i];
        #pragma unroll
        for (int h = 0; h < H; h++) {
            float ev = asrc[s * H + h] + adn[h];
            ev = ev > 0.f ? ev : 0.2f * ev;
            sm[h] += __expf(ev - mx[h]);
        }
    }
    #pragma unroll
    for (int h = 0; h < H; h++) {
        for (int o = 16; o > 0; o >>= 1)
            sm[h] += __shfl_xor_sync(0xffffffffu, sm[h], o);
        sm[h] = 1.f / sm[h];
    }
    float acc[CPL];
    int hed[CPL];
    #pragma unroll
    for (int j = 0; j < CPL; j++) {
        acc[j] = 0.f;
        int c = lane + 32 * j;
        hed[j] = (c < C) ? c / D : 0;
    }
    float adl = (lane < H) ? adn[lane] : 0.f;
    float mxl = (lane < H) ? mx[lane] : 0.f;
    float sml = (lane < H) ? sm[lane] : 0.f;
    for (int i = beg; i < end; i++) {
        int s = g_colsrc[i];
        float wt = 0.f;
        if (lane < H) {
            float ev = asrc[s * H + lane] + adl;
            ev = ev > 0.f ? ev : 0.2f * ev;
            wt = __expf(ev - mxl) * sml;
        }
        const __half* row = xw + (size_t)s * C;
        #pragma unroll
        for (int j = 0; j < CPL; j++) {
            float w = __shfl_sync(0xffffffffu, wt, hed[j]);
            int c = lane + 32 * j;
            if (c < C) acc[j] = fmaf(__half2float(row[c]), w, acc[j]);
        }
    }
    #pragma unroll
    for (int j = 0; j < CPL; j++) {
        int c = lane + 32 * j;
        if (c < C) s_agg[wl][c] = acc[j];
    }
    __syncwarp();
    for (int jc = lane; jc < D; jc += 32) {
        float v = 0.f;
        #pragma unroll
        for (int h = 0; h < H; h++) v += s_agg[wl][h * D + jc];
        out[node * D + jc] = v * (1.f / 6.f) + bias[jc] + skip[node * D + jc];
    }
}

// ---------------- launcher --------------------------------------------------
extern "C" void kernel_launch(void* const* d_in, const int* in_sizes, int n_in,
                              void* d_out, int out_size) {
    const float* x   = (const float*)d_in[0];
    const int*   ei  = (const int*)d_in[1];
    const float* W1  = (const float*)d_in[2];
    const float* as1 = (const float*)d_in[3];
    const float* ad1 = (const float*)d_in[4];
    const float* b1  = (const float*)d_in[5];
    const float* lw1 = (const float*)d_in[6];
    const float* lb1 = (const float*)d_in[7];
    const float* W2  = (const float*)d_in[8];
    const float* as2 = (const float*)d_in[9];
    const float* ad2 = (const float*)d_in[10];
    const float* b2  = (const float*)d_in[11];
    const float* lw2 = (const float*)d_in[12];
    const float* lb2 = (const float*)d_in[13];
    const float* W3  = (const float*)d_in[14];
    const float* as3 = (const float*)d_in[15];
    const float* ad3 = (const float*)d_in[16];
    const float* b3  = (const float*)d_in[17];
    const float* lw3 = (const float*)d_in[18];
    const float* lb3 = (const float*)d_in[19];
    float* out = (float*)d_out;

    int n = in_sizes[0] / FIN;
    int e = in_sizes[1] / 2;
    const int* srcp = ei;
    const int* dstp = ei + e;

    float *xw, *asrc, *adst, *skip, *hA, *hB;
    __half* xwh;
    cudaGetSymbolAddress((void**)&xw,   g_xw);
    cudaGetSymbolAddress((void**)&xwh,  g_xwh);
    cudaGetSymbolAddress((void**)&asrc, g_asrc);
    cudaGetSymbolAddress((void**)&adst, g_adst);
    cudaGetSymbolAddress((void**)&skip, g_skip);
    cudaGetSymbolAddress((void**)&hA,   g_hA);
    cudaGetSymbolAddress((void**)&hB,   g_hB);

    // ---- CSR build (dst-sorted adjacency incl. self-loops) ----
    k_init_counts<<<(n + 255) / 256, 256>>>(n);
    k_hist<<<(e + 255) / 256, 256>>>(dstp, e);
    k_scan<<<1, 1024>>>(n);
    k_zero_counts<<<(n + 255) / 256, 256>>>(n);
    k_scatter_self<<<(n + 255) / 256, 256>>>(n);
    k_scatter_edge<<<(e + 255) / 256, 256>>>(srcp, dstp, e);

    int nb64 = (n + 63) / 64;

    // ---- layer 1: GAT(50 -> 4x10, concat) + x@lw1 + lb1, elu ----
    gemm_kernel<FIN, float><<<dim3(nb64, 1), 256>>>(x, W1, nullptr, xw, n, 40);
    attn_kernel<4, 10><<<(n * 4 + 255) / 256, 256>>>(xw, as1, ad1, asrc, adst, n);
    gemm_kernel<FIN, float><<<dim3(nb64, 1), 256>>>(x, lw1, lb1, skip, n, 40);
    agg_concat_kernel<4, 10, 2><<<(n + 3) / 4, 128>>>(xw, asrc, adst, b1, skip, hA, n);

    // ---- layer 2: GAT(40 -> 4x10, concat) + hA@lw2 + lb2, elu ----
    gemm_kernel<HIDW, float><<<dim3(nb64, 1), 256>>>(hA, W2, nullptr, xw, n, 40);
    attn_kernel<4, 10><<<(n * 4 + 255) / 256, 256>>>(xw, as2, ad2, asrc, adst, n);
    gemm_kernel<HIDW, float><<<dim3(nb64, 1), 256>>>(hA, lw2, lb2, skip, n, 40);
    agg_concat_kernel<4, 10, 2><<<(n + 3) / 4, 128>>>(xw, asrc, adst, b2, skip, hB, n);

    // ---- layer 3: GAT(40 -> 6x121, mean) + hB@lw3 + lb3 ----
    gemm_kernel<HIDW, __half><<<dim3(nb64, (726 + 63) / 64), 256>>>(hB, W3, nullptr, xwh, n, 726);
    attn_kernel_h<6, 121><<<(n * 6 + 255) / 256, 256>>>(xwh, as3, ad3, asrc, adst, n);
    gemm_kernel<HIDW, float><<<dim3(nb64, (121 + 63) / 64), 256>>>(hB, lw3, lb3, skip, n, 121);
    agg_mean_kernel<<<(n + 3) / 4, 128>>>(xwh, asrc, adst, b3, skip, out, n);
}

// round 14
// speedup vs baseline: 1.3071x; 1.1531x over previous
#include <cuda_runtime.h>
#include <cuda_fp16.h>

#define NN 100000
#define EE 1600000
#define TOT (EE + NN)
#define FIN 50
#define HIDW 40
#define CDIM 121

// ---------------- scratch (device globals; no runtime allocation) ----------
__device__ int    g_cnt[NN];
__device__ int    g_rowptr[NN + 1];
__device__ int    g_colsrc[TOT];
__device__ float  g_xw[NN * HIDW];    // fp32 xw for layers 1,2 (40 cols)
__device__ __half g_xwh[NN * 726];    // fp16 xw for layer 3 (726 cols)
__device__ float  g_asrc[NN * 6];
__device__ float  g_adst[NN * 6];
__device__ float  g_skip[NN * CDIM];
__device__ float  g_hA[NN * HIDW];
__device__ float  g_hB[NN * HIDW];

// ---------------- CSR construction ----------------------------------------
__global__ void k_init_counts(int n) {
    int i = blockIdx.x * blockDim.x + threadIdx.x;
    if (i < n) g_cnt[i] = 1;   // self-loop
}

__global__ void k_hist(const int* __restrict__ dst, int e) {
    int i = blockIdx.x * blockDim.x + threadIdx.x;
    if (i < e) atomicAdd(&g_cnt[dst[i]], 1);
}

__global__ void k_scan(int n) {
    __shared__ int s_warp[32];
    __shared__ int s_carry;
    int tid = threadIdx.x, lane = tid & 31, w = tid >> 5;
    if (tid == 0) { s_carry = 0; g_rowptr[0] = 0; }
    __syncthreads();
    for (int base = 0; base < n; base += 1024) {
        int i = base + tid;
        int v = (i < n) ? g_cnt[i] : 0;
        int x = v;
        #pragma unroll
        for (int o = 1; o < 32; o <<= 1) {
            int y = __shfl_up_sync(0xffffffffu, x, o);
            if (lane >= o) x += y;
        }
        if (lane == 31) s_warp[w] = x;
        __syncthreads();
        if (w == 0) {
            int y = s_warp[lane];
            #pragma unroll
            for (int o = 1; o < 32; o <<= 1) {
                int z = __shfl_up_sync(0xffffffffu, y, o);
                if (lane >= o) y += z;
            }
            s_warp[lane] = y;
        }
        __syncthreads();
        int incl = x + (w > 0 ? s_warp[w - 1] : 0) + s_carry;
        if (i < n) g_rowptr[i + 1] = incl;
        __syncthreads();
        if (tid == 1023) s_carry = incl;
        __syncthreads();
    }
}

__global__ void k_zero_counts(int n) {
    int i = blockIdx.x * blockDim.x + threadIdx.x;
    if (i < n) g_cnt[i] = 0;
}

__global__ void k_scatter_self(int n) {
    int i = blockIdx.x * blockDim.x + threadIdx.x;
    if (i < n) {
        int pos = g_rowptr[i] + atomicAdd(&g_cnt[i], 1);
        g_colsrc[pos] = i;
    }
}

__global__ void k_scatter_edge(const int* __restrict__ src, const int* __restrict__ dst, int e) {
    int i = blockIdx.x * blockDim.x + threadIdx.x;
    if (i < e) {
        int d = dst[i];
        int pos = g_rowptr[d] + atomicAdd(&g_cnt[d], 1);
        g_colsrc[pos] = src[i];
    }
}

// ---------------- dense GEMM: out[n,C] = A[n,K] @ B[K,C] (+bias) ----------
template <int K, typename OUT_T>
__launch_bounds__(256)
__global__ void gemm_kernel(const float* __restrict__ A, const float* __restrict__ B,
                            const float* __restrict__ bias, OUT_T* __restrict__ out,
                            int n, int C) {
    __shared__ float sAT[K][68];   // [k][node]
    __shared__ float sB[K][68];    // [k][col]
    int n0 = blockIdx.x * 64, c0 = blockIdx.y * 64;
    for (int idx = threadIdx.x; idx < 64 * K; idx += 256) {
        int i = idx / K, k = idx - i * K;
        int node = n0 + i;
        sAT[k][i] = (node < n) ? A[(size_t)node * K + k] : 0.f;
    }
    for (int idx = threadIdx.x; idx < 64 * K; idx += 256) {
        int k = idx >> 6, j = idx & 63;
        int c = c0 + j;
        sB[k][j] = (c < C) ? B[k * C + c] : 0.f;
    }
    __syncthreads();
    int tx = threadIdx.x & 15, ty = threadIdx.x >> 4;
    float acc[4][4];
    #pragma unroll
    for (int i = 0; i < 4; i++)
        #pragma unroll
        for (int j = 0; j < 4; j++) acc[i][j] = 0.f;
    #pragma unroll 10
    for (int k = 0; k < K; k++) {
        float a[4], b[4];
        #pragma unroll
        for (int i = 0; i < 4; i++) a[i] = sAT[k][ty * 4 + i];
        #pragma unroll
        for (int j = 0; j < 4; j++) b[j] = sB[k][tx * 4 + j];
        #pragma unroll
        for (int i = 0; i < 4; i++)
            #pragma unroll
            for (int j = 0; j < 4; j++) acc[i][j] = fmaf(a[i], b[j], acc[i][j]);
    }
    #pragma unroll
    for (int i = 0; i < 4; i++) {
        int node = n0 + ty * 4 + i;
        if (node >= n) continue;
        #pragma unroll
        for (int j = 0; j < 4; j++) {
            int c = c0 + tx * 4 + j;
            if (c < C) {
                float v = acc[i][j] + (bias ? bias[c] : 0.f);
                out[(size_t)node * C + c] = (OUT_T)v;
            }
        }
    }
}

// ---------------- attention coefficients (fp32 xw) -------------------------
template <int H, int D>
__global__ void attn_kernel(const float* __restrict__ xw, const float* __restrict__ av,
                            const float* __restrict__ adv, float* __restrict__ asrc,
                            float* __restrict__ adst, int n) {
    int idx = blockIdx.x * blockDim.x + threadIdx.x;
    if (idx >= n * H) return;
    int node = idx / H, h = idx - node * H;
    const float* row = xw + (size_t)node * (H * D) + h * D;
    float s1 = 0.f, s2 = 0.f;
    #pragma unroll 8
    for (int d = 0; d < D; d++) {
        float v = row[d];
        s1 = fmaf(v, av[h * D + d], s1);
        s2 = fmaf(v, adv[h * D + d], s2);
    }
    asrc[idx] = s1;
    adst[idx] = s2;
}

// attention coefficients reading fp16 xw (layer 3)
template <int H, int D>
__global__ void attn_kernel_h(const __half* __restrict__ xw, const float* __restrict__ av,
                              const float* __restrict__ adv, float* __restrict__ asrc,
                              float* __restrict__ adst, int n) {
    int idx = blockIdx.x * blockDim.x + threadIdx.x;
    if (idx >= n * H) return;
    int node = idx / H, h = idx - node * H;
    const __half* row = xw + (size_t)node * (H * D) + h * D;
    float s1 = 0.f, s2 = 0.f;
    #pragma unroll 11
    for (int d = 0; d < D; d++) {
        float v = __half2float(row[d]);
        s1 = fmaf(v, av[h * D + d], s1);
        s2 = fmaf(v, adv[h * D + d], s2);
    }
    asrc[idx] = s1;
    adst[idx] = s2;
}

// ---------------- GAT aggregation: warp per node, chunked smem weights -----
// Per 32-edge chunk: each lane computes its edge's H softmax weights (one
// dense exp per edge-head) into shared memory and accumulates the sum; the
// warp then gathers values for the chunk reading weights from smem.
// Normalization (1/sum) is applied once in the epilogue.
// concat version (layers 1,2): out = elu(agg + bias + skip)
template <int H, int D, int CPL>
__launch_bounds__(128)
__global__ void agg_concat_kernel(const float* __restrict__ xw,
                                  const float* __restrict__ asrc,
                                  const float* __restrict__ adst,
                                  const float* __restrict__ bias,
                                  const float* __restrict__ skip,
                                  float* __restrict__ out, int n) {
    constexpr int C = H * D;
    __shared__ float s_w[4][32][H];
    __shared__ int   s_s[4][32];
    int node = (blockIdx.x * blockDim.x + threadIdx.x) >> 5;
    int lane = threadIdx.x & 31;
    int wid = threadIdx.x >> 5;
    if (node >= n) return;
    int beg = g_rowptr[node], end = g_rowptr[node + 1];
    float adn[H], sum[H];
    #pragma unroll
    for (int h = 0; h < H; h++) { adn[h] = adst[node * H + h]; sum[h] = 0.f; }
    float acc[CPL];
    int hed[CPL];
    #pragma unroll
    for (int j = 0; j < CPL; j++) {
        acc[j] = 0.f;
        int c = lane + 32 * j;
        hed[j] = (c < C) ? c / D : 0;
    }
    for (int base = beg; base < end; base += 32) {
        int i = base + lane;
        int cnt = min(32, end - base);
        if (i < end) {
            int s = g_colsrc[i];
            s_s[wid][lane] = s;
            #pragma unroll
            for (int h = 0; h < H; h++) {
                float ev = asrc[s * H + h] + adn[h];
                ev = ev > 0.f ? ev : 0.2f * ev;
                float wv = __expf(ev);
                sum[h] += wv;
                s_w[wid][lane][h] = wv;
            }
        }
        __syncwarp();
        for (int e = 0; e < cnt; e++) {
            int s = s_s[wid][e];
            const float* row = xw + (size_t)s * C;
            #pragma unroll
            for (int j = 0; j < CPL; j++) {
                int c = lane + 32 * j;
                if (c < C) acc[j] = fmaf(row[c], s_w[wid][e][hed[j]], acc[j]);
            }
        }
        __syncwarp();
    }
    // reduce sums (all lanes end with full sums), normalize in epilogue
    #pragma unroll
    for (int h = 0; h < H; h++) {
        for (int o = 16; o > 0; o >>= 1)
            sum[h] += __shfl_xor_sync(0xffffffffu, sum[h], o);
        sum[h] = 1.f / sum[h];
    }
    #pragma unroll
    for (int j = 0; j < CPL; j++) {
        int c = lane + 32 * j;
        if (c < C) {
            float iv = 0.f;
            #pragma unroll
            for (int h = 0; h < H; h++)
                if (hed[j] == h) iv = sum[h];
            float v = acc[j] * iv + bias[c] + skip[node * C + c];
            out[node * C + c] = v > 0.f ? v : (__expf(v) - 1.f);
        }
    }
}

// mean version (layer 3, heads=6, D=121, fp16 values): out = mean_h(agg) + bias + skip
__launch_bounds__(128)
__global__ void agg_mean_kernel(const __half* __restrict__ xw,
                                const float* __restrict__ asrc,
                                const float* __restrict__ adst,
                                const float* __restrict__ bias,
                                const float* __restrict__ skip,
                                float* __restrict__ out, int n) {
    constexpr int H = 6, D = 121, C = 726, CPL = 23;
    __shared__ float s_agg[4][C];
    __shared__ float s_w[4][32][H];
    __shared__ int   s_s[4][32];
    int node = (blockIdx.x * blockDim.x + threadIdx.x) >> 5;
    int lane = threadIdx.x & 31;
    int wid = threadIdx.x >> 5;
    if (node >= n) return;
    int beg = g_rowptr[node], end = g_rowptr[node + 1];
    float adn[H], sum[H];
    #pragma unroll
    for (int h = 0; h < H; h++) { adn[h] = adst[node * H + h]; sum[h] = 0.f; }
    float acc[CPL];
    int hed[CPL];
    #pragma unroll
    for (int j = 0; j < CPL; j++) {
        acc[j] = 0.f;
        int c = lane + 32 * j;
        hed[j] = (c < C) ? c / D : 0;
    }
    for (int base = beg; base < end; base += 32) {
        int i = base + lane;
        int cnt = min(32, end - base);
        if (i < end) {
            int s = g_colsrc[i];
            s_s[wid][lane] = s;
            #pragma unroll
            for (int h = 0; h < H; h++) {
                float ev = asrc[s * H + h] + adn[h];
                ev = ev > 0.f ? ev : 0.2f * ev;
                float wv = __expf(ev);
                sum[h] += wv;
                s_w[wid][lane][h] = wv;
            }
        }
        __syncwarp();
        for (int e = 0; e < cnt; e++) {
            int s = s_s[wid][e];
            const __half* row = xw + (size_t)s * C;
            #pragma unroll
            for (int j = 0; j < CPL; j++) {
                int c = lane + 32 * j;
                if (c < C) acc[j] = fmaf(__half2float(row[c]), s_w[wid][e][hed[j]], acc[j]);
            }
        }
        __syncwarp();
    }
    #pragma unroll
    for (int h = 0; h < H; h++) {
        for (int o = 16; o > 0; o >>= 1)
            sum[h] += __shfl_xor_sync(0xffffffffu, sum[h], o);
        sum[h] = 1.f / sum[h];
    }
    #pragma unroll
    for (int j = 0; j < CPL; j++) {
        int c = lane + 32 * j;
        if (c < C) {
            float iv = 0.f;
            #pragma unroll
            for (int h = 0; h < H; h++)
                if (hed[j] == h) iv = sum[h];
            s_agg[wid][c] = acc[j] * iv;
        }
    }
    __syncwarp();
    for (int jc = lane; jc < D; jc += 32) {
        float v = 0.f;
        #pragma unroll
        for (int h = 0; h < H; h++) v += s_agg[wid][h * D + jc];
        out[node * D + jc] = v * (1.f / 6.f) + bias[jc] + skip[node * D + jc];
    }
}

// ---------------- launcher --------------------------------------------------
extern "C" void kernel_launch(void* const* d_in, const int* in_sizes, int n_in,
                              void* d_out, int out_size) {
    const float* x   = (const float*)d_in[0];
    const int*   ei  = (const int*)d_in[1];
    const float* W1  = (const float*)d_in[2];
    const float* as1 = (const float*)d_in[3];
    const float* ad1 = (const float*)d_in[4];
    const float* b1  = (const float*)d_in[5];
    const float* lw1 = (const float*)d_in[6];
    const float* lb1 = (const float*)d_in[7];
    const float* W2  = (const float*)d_in[8];
    const float* as2 = (const float*)d_in[9];
    const float* ad2 = (const float*)d_in[10];
    const float* b2  = (const float*)d_in[11];
    const float* lw2 = (const float*)d_in[12];
    const float* lb2 = (const float*)d_in[13];
    const float* W3  = (const float*)d_in[14];
    const float* as3 = (const float*)d_in[15];
    const float* ad3 = (const float*)d_in[16];
    const float* b3  = (const float*)d_in[17];
    const float* lw3 = (const float*)d_in[18];
    const float* lb3 = (const float*)d_in[19];
    float* out = (float*)d_out;

    int n = in_sizes[0] / FIN;
    int e = in_sizes[1] / 2;
    const int* srcp = ei;
    const int* dstp = ei + e;

    float *xw, *asrc, *adst, *skip, *hA, *hB;
    __half* xwh;
    cudaGetSymbolAddress((void**)&xw,   g_xw);
    cudaGetSymbolAddress((void**)&xwh,  g_xwh);
    cudaGetSymbolAddress((void**)&asrc, g_asrc);
    cudaGetSymbolAddress((void**)&adst, g_adst);
    cudaGetSymbolAddress((void**)&skip, g_skip);
    cudaGetSymbolAddress((void**)&hA,   g_hA);
    cudaGetSymbolAddress((void**)&hB,   g_hB);

    // ---- CSR build (dst-sorted adjacency incl. self-loops) ----
    k_init_counts<<<(n + 255) / 256, 256>>>(n);
    k_hist<<<(e + 255) / 256, 256>>>(dstp, e);
    k_scan<<<1, 1024>>>(n);
    k_zero_counts<<<(n + 255) / 256, 256>>>(n);
    k_scatter_self<<<(n + 255) / 256, 256>>>(n);
    k_scatter_edge<<<(e + 255) / 256, 256>>>(srcp, dstp, e);

    int nb64 = (n + 63) / 64;

    // ---- layer 1: GAT(50 -> 4x10, concat) + x@lw1 + lb1, elu ----
    gemm_kernel<FIN, float><<<dim3(nb64, 1), 256>>>(x, W1, nullptr, xw, n, 40);
    attn_kernel<4, 10><<<(n * 4 + 255) / 256, 256>>>(xw, as1, ad1, asrc, adst, n);
    gemm_kernel<FIN, float><<<dim3(nb64, 1), 256>>>(x, lw1, lb1, skip, n, 40);
    agg_concat_kernel<4, 10, 2><<<(n + 3) / 4, 128>>>(xw, asrc, adst, b1, skip, hA, n);

    // ---- layer 2: GAT(40 -> 4x10, concat) + hA@lw2 + lb2, elu ----
    gemm_kernel<HIDW, float><<<dim3(nb64, 1), 256>>>(hA, W2, nullptr, xw, n, 40);
    attn_kernel<4, 10><<<(n * 4 + 255) / 256, 256>>>(xw, as2, ad2, asrc, adst, n);
    gemm_kernel<HIDW, float><<<dim3(nb64, 1), 256>>>(hA, lw2, lb2, skip, n, 40);
    agg_concat_kernel<4, 10, 2><<<(n + 3) / 4, 128>>>(xw, asrc, adst, b2, skip, hB, n);

    // ---- layer 3: GAT(40 -> 6x121, mean) + hB@lw3 + lb3 ----
    gemm_kernel<HIDW, __half><<<dim3(nb64, (726 + 63) / 64), 256>>>(hB, W3, nullptr, xwh, n, 726);
    attn_kernel_h<6, 121><<<(n * 6 + 255) / 256, 256>>>(xwh, as3, ad3, asrc, adst, n);
    gemm_kernel<HIDW, float><<<dim3(nb64, (121 + 63) / 64), 256>>>(hB, lw3, lb3, skip, n, 121);
    agg_mean_kernel<<<(n + 3) / 4, 128>>>(xwh, asrc, adst, b3, skip, out, n);
}